// round 9
// baseline (speedup 1.0000x reference)
#include <cuda_runtime.h>
#include <cuda_bf16.h>

// Problem constants (fixed shapes per reference)
#define E_TOTAL   3200000
#define NN        100000
#define EDGE_DIM  64
#define ADDED     24
#define H_DIM     256
#define KDIM      280
#define OUT_DIM   256

#define NBLK      391      // ceil(NN/256) for scans

// ---- scratch (device globals; no runtime allocation) ----
__device__ unsigned g_deg[NN];          // in-degree
__device__ unsigned g_bsum[512];        // per-scan-block sums (>= NBLK)
__device__ unsigned g_off[NN];          // CSR start offsets
__device__ unsigned g_cursor[NN];       // fill cursors
__device__ int      g_eid[E_TOTAL];     // CSR edge ids
__device__ float    g_S[NN * EDGE_DIM]; // per-node summed edge features (25.6 MB)
__device__ float    g_B2[65 * 256];     // rows 0..63: W_msg@W1b ; row 64: b_msg@W1b

// ---------------- helpers ----------------
__device__ __forceinline__ unsigned cvt_tf32(float f) {
    unsigned u;
    asm("cvt.rna.tf32.f32 %0, %1;" : "=r"(u) : "f"(f));
    return u;
}
__device__ __forceinline__ void mma_tf32(float& d0, float& d1, float& d2, float& d3,
                                         unsigned a0, unsigned a1, unsigned a2, unsigned a3,
                                         unsigned b0, unsigned b1) {
    asm volatile(
        "mma.sync.aligned.m16n8k8.row.col.f32.tf32.tf32.f32 "
        "{%0,%1,%2,%3}, {%4,%5,%6,%7}, {%8,%9}, {%0,%1,%2,%3};"
        : "+f"(d0), "+f"(d1), "+f"(d2), "+f"(d3)
        : "r"(a0), "r"(a1), "r"(a2), "r"(a3), "r"(b0), "r"(b1));
}

// ============================================================================
// Kernel: zero degrees (blocks 65..) + W2 precompute (blocks 0..64)
// B2[0:64] = W_msg @ W1[256:280], B2[64] = b_msg @ W1[256:280]
// ============================================================================
__global__ void init_kernel(const float* __restrict__ W_msg,
                            const float* __restrict__ b_msg,
                            const float* __restrict__ W1) {
    if (blockIdx.x < 65) {
        const int r = blockIdx.x;     // 0..64
        const int c = threadIdx.x;    // 0..255
        float acc = 0.f;
#pragma unroll
        for (int j = 0; j < ADDED; j++) {
            const float a = (r < EDGE_DIM) ? W_msg[r * ADDED + j] : b_msg[j];
            acc += a * W1[(long long)(H_DIM + j) * OUT_DIM + c];
        }
        g_B2[r * 256 + c] = acc;
    } else {
        const int i = (blockIdx.x - 65) * 256 + threadIdx.x;
        if (i < NN) g_deg[i] = 0u;
    }
}

// ============================================================================
// CSR build
// ============================================================================
__global__ void hist_kernel(const int* __restrict__ dst_idx) {
    int e = blockIdx.x * blockDim.x + threadIdx.x;
    if (e < E_TOTAL) atomicAdd(&g_deg[dst_idx[e]], 1u);
}

__global__ void scan1_kernel() {
    __shared__ unsigned s[256];
    const int t = threadIdx.x;
    const int n = blockIdx.x * 256 + t;
    s[t] = (n < NN) ? g_deg[n] : 0u;
    __syncthreads();
#pragma unroll
    for (int d = 128; d > 0; d >>= 1) {
        if (t < d) s[t] += s[t + d];
        __syncthreads();
    }
    if (t == 0) g_bsum[blockIdx.x] = s[0];
}

__global__ void scan2_kernel() {
    __shared__ unsigned s[512];
    const int t = threadIdx.x;
    s[t] = (t < NBLK) ? g_bsum[t] : 0u;
    __syncthreads();
#pragma unroll
    for (int d = 1; d < 512; d <<= 1) {
        unsigned v = (t >= d) ? s[t - d] : 0u;
        __syncthreads();
        s[t] += v;
        __syncthreads();
    }
    if (t < NBLK) g_bsum[t] = (t == 0) ? 0u : s[t - 1];
}

__global__ void scan3_kernel() {
    __shared__ unsigned s[256];
    const int t = threadIdx.x;
    const int n = blockIdx.x * 256 + t;
    const unsigned d = (n < NN) ? g_deg[n] : 0u;
    s[t] = d;
    __syncthreads();
#pragma unroll
    for (int dd = 1; dd < 256; dd <<= 1) {
        unsigned v = (t >= dd) ? s[t - dd] : 0u;
        __syncthreads();
        s[t] += v;
        __syncthreads();
    }
    if (n < NN) {
        const unsigned off = g_bsum[blockIdx.x] + s[t] - d;   // exclusive
        g_off[n] = off;
        g_cursor[n] = off;
    }
}

__global__ void fill_kernel(const int* __restrict__ dst_idx) {
    int e = blockIdx.x * blockDim.x + threadIdx.x;
    if (e < E_TOTAL) {
        const unsigned pos = atomicAdd(&g_cursor[dst_idx[e]], 1u);
        g_eid[pos] = e;
    }
}

// ============================================================================
// Gather: S[n] = sum of edge_feat rows of node n's incoming edges (no atomics)
// One warp per node; two half-warps, 4 edges in flight each.
// ============================================================================
__global__ __launch_bounds__(256) void gather_kernel(
    const float* __restrict__ edge_feat)   // [E, 64]
{
    const int tid = threadIdx.x;
    const int warp = tid >> 5;
    const int lane = tid & 31;
    const int hw  = lane >> 4;     // half-warp 0/1
    const int l16 = lane & 15;     // lane in half-warp -> dims 4*l16..+3

    const int n = blockIdx.x * 8 + warp;
    if (n >= NN) return;

    const unsigned off = g_off[n];
    const unsigned deg = g_deg[n];

    float4 acc = make_float4(0.f, 0.f, 0.f, 0.f);
    unsigned i = hw;
    // 4 edges in flight per half-warp
    for (; i + 6 < deg; i += 8) {
        const int e0 = g_eid[off + i];
        const int e1 = g_eid[off + i + 2];
        const int e2 = g_eid[off + i + 4];
        const int e3 = g_eid[off + i + 6];
        const float4 v0 = *reinterpret_cast<const float4*>(
            edge_feat + (long long)e0 * EDGE_DIM + 4 * l16);
        const float4 v1 = *reinterpret_cast<const float4*>(
            edge_feat + (long long)e1 * EDGE_DIM + 4 * l16);
        const float4 v2 = *reinterpret_cast<const float4*>(
            edge_feat + (long long)e2 * EDGE_DIM + 4 * l16);
        const float4 v3 = *reinterpret_cast<const float4*>(
            edge_feat + (long long)e3 * EDGE_DIM + 4 * l16);
        acc.x += (v0.x + v1.x) + (v2.x + v3.x);
        acc.y += (v0.y + v1.y) + (v2.y + v3.y);
        acc.z += (v0.z + v1.z) + (v2.z + v3.z);
        acc.w += (v0.w + v1.w) + (v2.w + v3.w);
    }
    for (; i < deg; i += 2) {
        const int e = g_eid[off + i];
        const float4 v = *reinterpret_cast<const float4*>(
            edge_feat + (long long)e * EDGE_DIM + 4 * l16);
        acc.x += v.x; acc.y += v.y; acc.z += v.z; acc.w += v.w;
    }
    acc.x += __shfl_xor_sync(0xffffffffu, acc.x, 16);
    acc.y += __shfl_xor_sync(0xffffffffu, acc.y, 16);
    acc.z += __shfl_xor_sync(0xffffffffu, acc.z, 16);
    acc.w += __shfl_xor_sync(0xffffffffu, acc.w, 16);
    if (hw == 0)
        *reinterpret_cast<float4*>(g_S + (long long)n * EDGE_DIM + 4 * l16) = acc;
}

// ============================================================================
// Node GEMM: out = relu([h | norm*S] @ [W1a; W2] + norm*deg*v + b1)
// K = 320 exactly (20 k-tiles of 16). Double-buffered tf32 mma.
// Block = 128 rows x 128 cols, 256 threads = 8 warps (4m x 2n).
// The rank-1 deg term (v = b_msg@W1b = B2 row 64) is added in the epilogue.
// ============================================================================
#define ROW_TILES 782     // 782*128 = 100096 >= NN
#define NKT 20            // k-tiles of 16 over K=320

__global__ __launch_bounds__(256, 2) void node_kernel(
    const float* __restrict__ h,      // [NN, 256]
    const float* __restrict__ norm,   // [NN, 1]
    const float* __restrict__ W1,     // [280, 256]
    const float* __restrict__ b1,     // [256]
    float* __restrict__ out)          // [NN, 256]
{
    __shared__ __align__(16) unsigned As[2][128][20];
    __shared__ __align__(16) unsigned Ws[2][16][136];

    const int tid = threadIdx.x;
    const int wid = tid >> 5;
    const int lane = tid & 31;
    const int g  = lane >> 2;
    const int tg = lane & 3;
    const int wm = wid & 3;
    const int wn = wid >> 2;
    const int rt = blockIdx.x >> 1;
    const int cb = blockIdx.x & 1;
    const int row0 = rt * 128;
    const int col0 = cb * 128;

    const int arow = tid >> 1;
    const int aq   = (tid & 1) * 8;
    const int brow = tid >> 4;
    const int bcol = (tid & 15) * 4;

    const int agrow = row0 + arow;
    const bool arv = (agrow < NN);
    const float nr = arv ? norm[agrow] : 0.f;

    float acc[2][8][4];
#pragma unroll
    for (int mt = 0; mt < 2; mt++)
#pragma unroll
        for (int nf = 0; nf < 8; nf++)
#pragma unroll
            for (int i = 0; i < 4; i++) acc[mt][nf][i] = 0.f;

    float4 av[2], bv[2];

    auto fetchA = [&](int ka) -> float4 {
        float4 v = make_float4(0.f, 0.f, 0.f, 0.f);
        if (arv) {
            if (ka < H_DIM) {
                v = *reinterpret_cast<const float4*>(h + (long long)agrow * H_DIM + ka);
            } else {
                v = *reinterpret_cast<const float4*>(
                    g_S + (long long)agrow * EDGE_DIM + (ka - H_DIM));
                v.x *= nr; v.y *= nr; v.z *= nr; v.w *= nr;
            }
        }
        return v;
    };

    auto load_tile = [&](int kt) {
        const int k0 = kt * 16;
        av[0] = fetchA(k0 + aq);
        av[1] = fetchA(k0 + aq + 4);
        const int kb = k0 + brow;
        if (kb < H_DIM) {
            bv[0] = *reinterpret_cast<const float4*>(
                W1 + (long long)kb * OUT_DIM + col0 + bcol);
            bv[1] = *reinterpret_cast<const float4*>(
                W1 + (long long)kb * OUT_DIM + col0 + bcol + 64);
        } else {
            bv[0] = *reinterpret_cast<const float4*>(
                g_B2 + (kb - H_DIM) * 256 + col0 + bcol);
            bv[1] = *reinterpret_cast<const float4*>(
                g_B2 + (kb - H_DIM) * 256 + col0 + bcol + 64);
        }
    };

    auto cvt_sts = [&](int buf) {
        unsigned* ad = &As[buf][arow][aq];
        ad[0] = cvt_tf32(av[0].x); ad[1] = cvt_tf32(av[0].y);
        ad[2] = cvt_tf32(av[0].z); ad[3] = cvt_tf32(av[0].w);
        ad[4] = cvt_tf32(av[1].x); ad[5] = cvt_tf32(av[1].y);
        ad[6] = cvt_tf32(av[1].z); ad[7] = cvt_tf32(av[1].w);
        unsigned* bd0 = &Ws[buf][brow][bcol];
        bd0[0] = cvt_tf32(bv[0].x); bd0[1] = cvt_tf32(bv[0].y);
        bd0[2] = cvt_tf32(bv[0].z); bd0[3] = cvt_tf32(bv[0].w);
        unsigned* bd1 = &Ws[buf][brow][bcol + 64];
        bd1[0] = cvt_tf32(bv[1].x); bd1[1] = cvt_tf32(bv[1].y);
        bd1[2] = cvt_tf32(bv[1].z); bd1[3] = cvt_tf32(bv[1].w);
    };

    load_tile(0);
    cvt_sts(0);
    __syncthreads();

    for (int kt = 0; kt < NKT; kt++) {
        const int buf = kt & 1;
        if (kt + 1 < NKT) load_tile(kt + 1);

#pragma unroll
        for (int ks = 0; ks < 2; ks++) {
            const int kk = ks * 8;
            // hoist B fragments once per k-step, reuse across both m-tiles
            unsigned b0r[8], b1r[8];
#pragma unroll
            for (int nf = 0; nf < 8; nf++) {
                const int cc = wn * 64 + nf * 8;
                b0r[nf] = Ws[buf][kk + tg][cc + g];
                b1r[nf] = Ws[buf][kk + tg + 4][cc + g];
            }
#pragma unroll
            for (int mt = 0; mt < 2; mt++) {
                const int rb = wm * 32 + mt * 16;
                const unsigned a0 = As[buf][rb + g][kk + tg];
                const unsigned a1 = As[buf][rb + g + 8][kk + tg];
                const unsigned a2 = As[buf][rb + g][kk + tg + 4];
                const unsigned a3 = As[buf][rb + g + 8][kk + tg + 4];
#pragma unroll
                for (int nf = 0; nf < 8; nf++) {
                    mma_tf32(acc[mt][nf][0], acc[mt][nf][1],
                             acc[mt][nf][2], acc[mt][nf][3],
                             a0, a1, a2, a3, b0r[nf], b1r[nf]);
                }
            }
        }

        if (kt + 1 < NKT) cvt_sts((kt + 1) & 1);
        __syncthreads();
    }

    // epilogue: + norm*deg*v + bias, relu, store
    // this thread's 4 output rows: base + {0, 8, 16, 24}
    const int rbase = row0 + wm * 32 + g;
    float nd[4];
#pragma unroll
    for (int q = 0; q < 4; q++) {
        const int r = rbase + 8 * q;
        nd[q] = (r < NN) ? norm[r] * (float)g_deg[r] : 0.f;
    }

#pragma unroll
    for (int nf = 0; nf < 8; nf++) {
        const int col = col0 + wn * 64 + nf * 8 + 2 * tg;
        const float2 bb = *reinterpret_cast<const float2*>(b1 + col);
        const float2 vv = *reinterpret_cast<const float2*>(g_B2 + 64 * 256 + col);
#pragma unroll
        for (int mt = 0; mt < 2; mt++) {
            const int r = rbase + mt * 16;
            const float ndr = nd[mt * 2];
            if (r < NN) {
                float2 o;
                o.x = fmaxf(acc[mt][nf][0] + bb.x + ndr * vv.x, 0.f);
                o.y = fmaxf(acc[mt][nf][1] + bb.y + ndr * vv.y, 0.f);
                *reinterpret_cast<float2*>(out + (long long)r * OUT_DIM + col) = o;
            }
            const int r2 = r + 8;
            const float ndr2 = nd[mt * 2 + 1];
            if (r2 < NN) {
                float2 o;
                o.x = fmaxf(acc[mt][nf][2] + bb.x + ndr2 * vv.x, 0.f);
                o.y = fmaxf(acc[mt][nf][3] + bb.y + ndr2 * vv.y, 0.f);
                *reinterpret_cast<float2*>(out + (long long)r2 * OUT_DIM + col) = o;
            }
        }
    }
}

// ---------------- launch ----------------
extern "C" void kernel_launch(void* const* d_in, const int* in_sizes, int n_in,
                              void* d_out, int out_size) {
    const float* h         = (const float*)d_in[0];
    const float* edge_feat = (const float*)d_in[1];
    const float* norm      = (const float*)d_in[2];
    const float* W_msg     = (const float*)d_in[3];
    const float* b_msg     = (const float*)d_in[4];
    const float* W1        = (const float*)d_in[5];
    const float* b1        = (const float*)d_in[6];
    const int*   dst_idx   = (const int*)d_in[7];
    float* out = (float*)d_out;

    // init: W2/v precompute + zero degrees
    init_kernel<<<65 + NBLK, 256>>>(W_msg, b_msg, W1);

    // CSR build
    hist_kernel<<<(E_TOTAL + 255) / 256, 256>>>(dst_idx);
    scan1_kernel<<<NBLK, 256>>>();
    scan2_kernel<<<1, 512>>>();
    scan3_kernel<<<NBLK, 256>>>();
    fill_kernel<<<(E_TOTAL + 255) / 256, 256>>>(dst_idx);

    // gather-sum raw edge features (atomic-free)
    gather_kernel<<<(NN + 7) / 8, 256>>>(edge_feat);

    // fused node GEMM: [h | norm*S] @ [W1a; W2] + norm*deg*v + b1, ReLU
    node_kernel<<<ROW_TILES * 2, 256>>>(h, norm, W1, b1, out);
}

// round 10
// speedup vs baseline: 1.1005x; 1.1005x over previous
#include <cuda_runtime.h>
#include <cuda_fp16.h>

// Problem constants (fixed shapes per reference)
#define E_TOTAL   3200000
#define NN        100000
#define EDGE_DIM  64
#define ADDED     24
#define H_DIM     256
#define KDIM      280
#define OUT_DIM   256

#define NBLK      391      // ceil(NN/256) for scans
#define NKT       20       // node k-tiles of 16 over K=320

// ---- scratch (device globals; no runtime allocation) ----
__device__ unsigned g_deg[NN];          // in-degree
__device__ unsigned g_bsum[512];        // per-scan-block sums (>= NBLK)
__device__ unsigned g_off[NN];          // CSR start offsets
__device__ unsigned g_cursor[NN];       // fill cursors
__device__ int      g_eid[E_TOTAL];     // CSR edge ids
__device__ float    g_S[NN * EDGE_DIM]; // per-node summed edge features (25.6 MB)
__device__ float    g_B2[65 * 256];     // rows 0..63: W_msg@W1b ; row 64: b_msg@W1b
// fp16 packed B: [kt][n][j] ; j=2*tg   -> {k=16kt+2tg,   16kt+2tg+1}
//                             j=2*tg+1 -> {k=16kt+2tg+8, 16kt+2tg+9}  (lo = k even)
__device__ unsigned g_Bpack[NKT * 256 * 8];

// ---------------- helpers ----------------
__device__ __forceinline__ unsigned f16x2_pack(float lo, float hi) {
    unsigned u;
    asm("cvt.rn.f16x2.f32 %0, %1, %2;" : "=r"(u) : "f"(hi), "f"(lo));
    return u;
}
__device__ __forceinline__ void mma_f16(float& d0, float& d1, float& d2, float& d3,
                                        unsigned a0, unsigned a1, unsigned a2, unsigned a3,
                                        unsigned b0, unsigned b1) {
    asm volatile(
        "mma.sync.aligned.m16n8k16.row.col.f32.f16.f16.f32 "
        "{%0,%1,%2,%3}, {%4,%5,%6,%7}, {%8,%9}, {%0,%1,%2,%3};"
        : "+f"(d0), "+f"(d1), "+f"(d2), "+f"(d3)
        : "r"(a0), "r"(a1), "r"(a2), "r"(a3), "r"(b0), "r"(b1));
}
__device__ __forceinline__ void ldsm_x4(unsigned& r0, unsigned& r1, unsigned& r2, unsigned& r3,
                                        unsigned saddr) {
    asm volatile("ldmatrix.sync.aligned.m8n8.x4.shared.b16 {%0,%1,%2,%3}, [%4];"
                 : "=r"(r0), "=r"(r1), "=r"(r2), "=r"(r3) : "r"(saddr));
}

// ============================================================================
// init: W2 precompute (blocks 0..64) + zero degrees (blocks 65..)
// ============================================================================
__global__ void init_kernel(const float* __restrict__ W_msg,
                            const float* __restrict__ b_msg,
                            const float* __restrict__ W1) {
    if (blockIdx.x < 65) {
        const int r = blockIdx.x;
        const int c = threadIdx.x;
        float acc = 0.f;
#pragma unroll
        for (int j = 0; j < ADDED; j++) {
            const float a = (r < EDGE_DIM) ? W_msg[r * ADDED + j] : b_msg[j];
            acc += a * W1[(long long)(H_DIM + j) * OUT_DIM + c];
        }
        g_B2[r * 256 + c] = acc;
    } else {
        const int i = (blockIdx.x - 65) * 256 + threadIdx.x;
        if (i < NN) g_deg[i] = 0u;
    }
}

// ============================================================================
// pack: build fp16 packed B from W1 (k<256) and g_B2 (k>=256). 20 blocks x 256.
// ============================================================================
__global__ void pack_kernel(const float* __restrict__ W1) {
    const int kt = blockIdx.x;    // 0..19
    const int n  = threadIdx.x;   // 0..255
#pragma unroll
    for (int j = 0; j < 8; j++) {
        const int tg = j >> 1;
        const int kk = (j & 1) ? (2 * tg + 8) : (2 * tg);
        const int k0 = kt * 16 + kk;
        float f0, f1;
        if (k0 < H_DIM) {
            f0 = W1[(long long)k0 * OUT_DIM + n];
            f1 = W1[(long long)(k0 + 1) * OUT_DIM + n];
        } else {
            f0 = g_B2[(k0 - H_DIM) * 256 + n];
            f1 = g_B2[(k0 + 1 - H_DIM) * 256 + n];
        }
        g_Bpack[(kt * 256 + n) * 8 + j] = f16x2_pack(f0, f1);
    }
}

// ============================================================================
// CSR build
// ============================================================================
__global__ void hist_kernel(const int* __restrict__ dst_idx) {
    int e = blockIdx.x * blockDim.x + threadIdx.x;
    if (e < E_TOTAL) atomicAdd(&g_deg[dst_idx[e]], 1u);
}

__global__ void scan1_kernel() {
    __shared__ unsigned s[256];
    const int t = threadIdx.x;
    const int n = blockIdx.x * 256 + t;
    s[t] = (n < NN) ? g_deg[n] : 0u;
    __syncthreads();
#pragma unroll
    for (int d = 128; d > 0; d >>= 1) {
        if (t < d) s[t] += s[t + d];
        __syncthreads();
    }
    if (t == 0) g_bsum[blockIdx.x] = s[0];
}

__global__ void scan2_kernel() {
    __shared__ unsigned s[512];
    const int t = threadIdx.x;
    s[t] = (t < NBLK) ? g_bsum[t] : 0u;
    __syncthreads();
#pragma unroll
    for (int d = 1; d < 512; d <<= 1) {
        unsigned v = (t >= d) ? s[t - d] : 0u;
        __syncthreads();
        s[t] += v;
        __syncthreads();
    }
    if (t < NBLK) g_bsum[t] = (t == 0) ? 0u : s[t - 1];
}

__global__ void scan3_kernel() {
    __shared__ unsigned s[256];
    const int t = threadIdx.x;
    const int n = blockIdx.x * 256 + t;
    const unsigned d = (n < NN) ? g_deg[n] : 0u;
    s[t] = d;
    __syncthreads();
#pragma unroll
    for (int dd = 1; dd < 256; dd <<= 1) {
        unsigned v = (t >= dd) ? s[t - dd] : 0u;
        __syncthreads();
        s[t] += v;
        __syncthreads();
    }
    if (n < NN) {
        const unsigned off = g_bsum[blockIdx.x] + s[t] - d;   // exclusive
        g_off[n] = off;
        g_cursor[n] = off;
    }
}

__global__ void fill_kernel(const int* __restrict__ dst_idx) {
    int e = blockIdx.x * blockDim.x + threadIdx.x;
    if (e < E_TOTAL) {
        const unsigned pos = atomicAdd(&g_cursor[dst_idx[e]], 1u);
        g_eid[pos] = e;
    }
}

// ============================================================================
// Gather: S[n] = sum of edge_feat rows of node n's incoming edges (no atomics)
// ============================================================================
__global__ __launch_bounds__(256) void gather_kernel(
    const float* __restrict__ edge_feat)   // [E, 64]
{
    const int tid = threadIdx.x;
    const int warp = tid >> 5;
    const int lane = tid & 31;
    const int hw  = lane >> 4;
    const int l16 = lane & 15;

    const int n = blockIdx.x * 8 + warp;
    if (n >= NN) return;

    const unsigned off = g_off[n];
    const unsigned deg = g_deg[n];

    float4 acc = make_float4(0.f, 0.f, 0.f, 0.f);
    unsigned i = hw;
    for (; i + 6 < deg; i += 8) {
        const int e0 = g_eid[off + i];
        const int e1 = g_eid[off + i + 2];
        const int e2 = g_eid[off + i + 4];
        const int e3 = g_eid[off + i + 6];
        const float4 v0 = *reinterpret_cast<const float4*>(
            edge_feat + (long long)e0 * EDGE_DIM + 4 * l16);
        const float4 v1 = *reinterpret_cast<const float4*>(
            edge_feat + (long long)e1 * EDGE_DIM + 4 * l16);
        const float4 v2 = *reinterpret_cast<const float4*>(
            edge_feat + (long long)e2 * EDGE_DIM + 4 * l16);
        const float4 v3 = *reinterpret_cast<const float4*>(
            edge_feat + (long long)e3 * EDGE_DIM + 4 * l16);
        acc.x += (v0.x + v1.x) + (v2.x + v3.x);
        acc.y += (v0.y + v1.y) + (v2.y + v3.y);
        acc.z += (v0.z + v1.z) + (v2.z + v3.z);
        acc.w += (v0.w + v1.w) + (v2.w + v3.w);
    }
    for (; i < deg; i += 2) {
        const int e = g_eid[off + i];
        const float4 v = *reinterpret_cast<const float4*>(
            edge_feat + (long long)e * EDGE_DIM + 4 * l16);
        acc.x += v.x; acc.y += v.y; acc.z += v.z; acc.w += v.w;
    }
    acc.x += __shfl_xor_sync(0xffffffffu, acc.x, 16);
    acc.y += __shfl_xor_sync(0xffffffffu, acc.y, 16);
    acc.z += __shfl_xor_sync(0xffffffffu, acc.z, 16);
    acc.w += __shfl_xor_sync(0xffffffffu, acc.w, 16);
    if (hw == 0)
        *reinterpret_cast<float4*>(g_S + (long long)n * EDGE_DIM + 4 * l16) = acc;
}

// ============================================================================
// Node GEMM: out = relu([h | norm*S]_f16 @ Bpack_f16 + norm*deg*v + b1)
// fp16 mma m16n8k16, fp32 accum. Block = 128x128, 256 thr, 8 warps (4m x 2n).
// A: smem [128][24] halves (48B rows, LDSM-conflict-free), frags via ldmatrix.x4.
// B: g_Bpack preconverted/packed; frags via conflict-free LDS.64.
// ============================================================================
#define ROW_TILES 782     // 782*128 = 100096 >= NN

__global__ __launch_bounds__(256, 2) void node_kernel(
    const float* __restrict__ h,      // [NN, 256]
    const float* __restrict__ norm,   // [NN, 1]
    const float* __restrict__ b1,     // [256]
    float* __restrict__ out)          // [NN, 256]
{
    __shared__ __align__(16) __half  As[2][128][24];     // 2 x 6 KB
    __shared__ __align__(16) unsigned Bs[2][128][8];     // 2 x 4 KB

    const int tid = threadIdx.x;
    const int wid = tid >> 5;
    const int lane = tid & 31;
    const int g  = lane >> 2;
    const int tg = lane & 3;
    const int wm = wid & 3;          // rows wm*32..+31
    const int wn = wid >> 2;         // cols wn*64..+63 (within 128-col tile)
    const int rt = blockIdx.x >> 1;
    const int cb = blockIdx.x & 1;
    const int row0 = rt * 128;
    const int col0 = cb * 128;

    // A loader role
    const int arow = tid >> 1;            // 0..127
    const int aq   = (tid & 1) * 8;       // k offset 0/8
    // B loader role: copy one uint4 of the 4KB packed tile
    const int bn   = tid >> 1;            // n 0..127
    const int bp   = tid & 1;             // uint4 half of the 8-u32 row

    const int agrow = row0 + arow;
    const bool arv = (agrow < NN);
    const float nr = arv ? norm[agrow] : 0.f;

    // ldmatrix source addresses (fixed per buffer/m-tile)
    unsigned lm_addr[2][2];
#pragma unroll
    for (int buf = 0; buf < 2; buf++)
#pragma unroll
        for (int mt = 0; mt < 2; mt++) {
            const int r = wm * 32 + mt * 16 + (lane & 15);
            const __half* p = &As[buf][r][(lane >> 4) * 8];
            lm_addr[buf][mt] = (unsigned)__cvta_generic_to_shared(p);
        }

    float acc[2][8][4];
#pragma unroll
    for (int mt = 0; mt < 2; mt++)
#pragma unroll
        for (int nf = 0; nf < 8; nf++)
#pragma unroll
            for (int i = 0; i < 4; i++) acc[mt][nf][i] = 0.f;

    float4 av0, av1;
    uint4 bq;

    auto load_tile = [&](int kt) {
        const int ka = kt * 16 + aq;
        av0 = make_float4(0.f, 0.f, 0.f, 0.f);
        av1 = make_float4(0.f, 0.f, 0.f, 0.f);
        if (arv) {
            if (ka < H_DIM) {
                av0 = *reinterpret_cast<const float4*>(h + (long long)agrow * H_DIM + ka);
                av1 = *reinterpret_cast<const float4*>(h + (long long)agrow * H_DIM + ka + 4);
            } else {
                av0 = *reinterpret_cast<const float4*>(
                    g_S + (long long)agrow * EDGE_DIM + (ka - H_DIM));
                av1 = *reinterpret_cast<const float4*>(
                    g_S + (long long)agrow * EDGE_DIM + (ka - H_DIM) + 4);
                av0.x *= nr; av0.y *= nr; av0.z *= nr; av0.w *= nr;
                av1.x *= nr; av1.y *= nr; av1.z *= nr; av1.w *= nr;
            }
        }
        bq = reinterpret_cast<const uint4*>(g_Bpack)[
            (kt * 256 + col0 + bn) * 2 + bp];
    };

    auto cvt_sts = [&](int buf) {
        uint4 a;
        a.x = f16x2_pack(av0.x, av0.y);
        a.y = f16x2_pack(av0.z, av0.w);
        a.z = f16x2_pack(av1.x, av1.y);
        a.w = f16x2_pack(av1.z, av1.w);
        *reinterpret_cast<uint4*>(&As[buf][arow][aq]) = a;
        *reinterpret_cast<uint4*>(&Bs[buf][bn][bp * 4]) = bq;
    };

    load_tile(0);
    cvt_sts(0);
    __syncthreads();

    for (int kt = 0; kt < NKT; kt++) {
        const int buf = kt & 1;
        if (kt + 1 < NKT) load_tile(kt + 1);

        // B fragments: 8 conflict-free LDS.64 (reused across both m-tiles)
        unsigned bfr0[8], bfr1[8];
#pragma unroll
        for (int nf = 0; nf < 8; nf++) {
            const int cc = wn * 64 + nf * 8;
            const unsigned long long bb =
                *reinterpret_cast<const unsigned long long*>(&Bs[buf][cc + g][2 * tg]);
            bfr0[nf] = (unsigned)bb;
            bfr1[nf] = (unsigned)(bb >> 32);
        }
#pragma unroll
        for (int mt = 0; mt < 2; mt++) {
            unsigned a0, a1, a2, a3;
            ldsm_x4(a0, a1, a2, a3, lm_addr[buf][mt]);
#pragma unroll
            for (int nf = 0; nf < 8; nf++) {
                mma_f16(acc[mt][nf][0], acc[mt][nf][1],
                        acc[mt][nf][2], acc[mt][nf][3],
                        a0, a1, a2, a3, bfr0[nf], bfr1[nf]);
            }
        }

        if (kt + 1 < NKT) cvt_sts((kt + 1) & 1);
        __syncthreads();
    }

    // epilogue: + norm*deg*v + bias, relu, store
    const int rbase = row0 + wm * 32 + g;
    float nd[4];
#pragma unroll
    for (int q = 0; q < 4; q++) {
        const int r = rbase + 8 * q;
        nd[q] = (r < NN) ? norm[r] * (float)g_deg[r] : 0.f;
    }

#pragma unroll
    for (int nf = 0; nf < 8; nf++) {
        const int col = col0 + wn * 64 + nf * 8 + 2 * tg;
        const float2 bb = *reinterpret_cast<const float2*>(b1 + col);
        const float2 vv = *reinterpret_cast<const float2*>(g_B2 + 64 * 256 + col);
#pragma unroll
        for (int mt = 0; mt < 2; mt++) {
            const int r = rbase + mt * 16;
            const float ndr = nd[mt * 2];
            if (r < NN) {
                float2 o;
                o.x = fmaxf(acc[mt][nf][0] + bb.x + ndr * vv.x, 0.f);
                o.y = fmaxf(acc[mt][nf][1] + bb.y + ndr * vv.y, 0.f);
                *reinterpret_cast<float2*>(out + (long long)r * OUT_DIM + col) = o;
            }
            const int r2 = r + 8;
            const float ndr2 = nd[mt * 2 + 1];
            if (r2 < NN) {
                float2 o;
                o.x = fmaxf(acc[mt][nf][2] + bb.x + ndr2 * vv.x, 0.f);
                o.y = fmaxf(acc[mt][nf][3] + bb.y + ndr2 * vv.y, 0.f);
                *reinterpret_cast<float2*>(out + (long long)r2 * OUT_DIM + col) = o;
            }
        }
    }
}

// ---------------- launch ----------------
extern "C" void kernel_launch(void* const* d_in, const int* in_sizes, int n_in,
                              void* d_out, int out_size) {
    const float* h         = (const float*)d_in[0];
    const float* edge_feat = (const float*)d_in[1];
    const float* norm      = (const float*)d_in[2];
    const float* W_msg     = (const float*)d_in[3];
    const float* b_msg     = (const float*)d_in[4];
    const float* W1        = (const float*)d_in[5];
    const float* b1        = (const float*)d_in[6];
    const int*   dst_idx   = (const int*)d_in[7];
    float* out = (float*)d_out;

    // init: W2/v precompute + zero degrees; then fp16-pack B
    init_kernel<<<65 + NBLK, 256>>>(W_msg, b_msg, W1);
    pack_kernel<<<NKT, 256>>>(W1);

    // CSR build
    hist_kernel<<<(E_TOTAL + 255) / 256, 256>>>(dst_idx);
    scan1_kernel<<<NBLK, 256>>>();
    scan2_kernel<<<1, 512>>>();
    scan3_kernel<<<NBLK, 256>>>();
    fill_kernel<<<(E_TOTAL + 255) / 256, 256>>>(dst_idx);

    // gather-sum raw edge features (atomic-free)
    gather_kernel<<<(NN + 7) / 8, 256>>>(edge_feat);

    // fused node GEMM (fp16 tensor cores) + rank-1 deg term + bias + ReLU
    node_kernel<<<ROW_TILES * 2, 256>>>(h, norm, b1, out);
}

// round 11
// speedup vs baseline: 1.2532x; 1.1387x over previous
#include <cuda_runtime.h>
#include <cuda_fp16.h>

// Problem constants (fixed shapes per reference)
#define E_TOTAL   3200000
#define NN        100000
#define EDGE_DIM  64
#define ADDED     24
#define H_DIM     256
#define KDIM      280
#define OUT_DIM   256

#define NBLK      391      // ceil(NN/256) for scans
#define NKT       20       // node k-tiles of 16 over K=320
#define NSTG      4        // cp.async pipeline stages

// ---- scratch (device globals; no runtime allocation) ----
__device__ unsigned g_deg[NN];
__device__ unsigned g_bsum[512];
__device__ unsigned g_off[NN];
__device__ unsigned g_cursor[NN];
__device__ int      g_eid[E_TOTAL];
__device__ float    g_B2[65 * 256];     // rows 0..63: W_msg@W1b ; row 64: b_msg@W1b
// fp16 A matrix [h | norm*S], row stride 320 halves. Rows >= NN stay zero.
__device__ __align__(16) __half g_Ah[100096 * 320];
// fp16 packed B (see R10 layout): [kt][n][8 u32]
__device__ __align__(16) unsigned g_Bpack[NKT * 256 * 8];

// ---------------- helpers ----------------
__device__ __forceinline__ unsigned f16x2_pack(float lo, float hi) {
    unsigned u;
    asm("cvt.rn.f16x2.f32 %0, %1, %2;" : "=r"(u) : "f"(hi), "f"(lo));
    return u;
}
__device__ __forceinline__ void mma_f16(float& d0, float& d1, float& d2, float& d3,
                                        unsigned a0, unsigned a1, unsigned a2, unsigned a3,
                                        unsigned b0, unsigned b1) {
    asm volatile(
        "mma.sync.aligned.m16n8k16.row.col.f32.f16.f16.f32 "
        "{%0,%1,%2,%3}, {%4,%5,%6,%7}, {%8,%9}, {%0,%1,%2,%3};"
        : "+f"(d0), "+f"(d1), "+f"(d2), "+f"(d3)
        : "r"(a0), "r"(a1), "r"(a2), "r"(a3), "r"(b0), "r"(b1));
}
__device__ __forceinline__ void ldsm_x4(unsigned& r0, unsigned& r1, unsigned& r2, unsigned& r3,
                                        unsigned saddr) {
    asm volatile("ldmatrix.sync.aligned.m8n8.x4.shared.b16 {%0,%1,%2,%3}, [%4];"
                 : "=r"(r0), "=r"(r1), "=r"(r2), "=r"(r3) : "r"(saddr));
}
__device__ __forceinline__ void cp_async16(unsigned saddr, const void* gptr) {
    asm volatile("cp.async.cg.shared.global [%0], [%1], 16;"
                 :: "r"(saddr), "l"(gptr));
}

// ============================================================================
// conv: g_Ah[:, 0:256] = fp16(h). 3.2M threads, 8 halves each.
// ============================================================================
__global__ void conv_kernel(const float* __restrict__ h) {
    const long long t = (long long)blockIdx.x * 256 + threadIdx.x;
    if (t < (long long)NN * 32) {
        const int row = (int)(t >> 5);
        const int kc  = (int)(t & 31) * 8;
        const float4 v0 = *reinterpret_cast<const float4*>(h + (long long)row * 256 + kc);
        const float4 v1 = *reinterpret_cast<const float4*>(h + (long long)row * 256 + kc + 4);
        uint4 o;
        o.x = f16x2_pack(v0.x, v0.y); o.y = f16x2_pack(v0.z, v0.w);
        o.z = f16x2_pack(v1.x, v1.y); o.w = f16x2_pack(v1.z, v1.w);
        *reinterpret_cast<uint4*>(g_Ah + (long long)row * 320 + kc) = o;
    }
}

// ============================================================================
// init: W2 precompute (blocks 0..64) + zero degrees (blocks 65..)
// ============================================================================
__global__ void init_kernel(const float* __restrict__ W_msg,
                            const float* __restrict__ b_msg,
                            const float* __restrict__ W1) {
    if (blockIdx.x < 65) {
        const int r = blockIdx.x;
        const int c = threadIdx.x;
        float acc = 0.f;
#pragma unroll
        for (int j = 0; j < ADDED; j++) {
            const float a = (r < EDGE_DIM) ? W_msg[r * ADDED + j] : b_msg[j];
            acc += a * W1[(long long)(H_DIM + j) * OUT_DIM + c];
        }
        g_B2[r * 256 + c] = acc;
    } else {
        const int i = (blockIdx.x - 65) * 256 + threadIdx.x;
        if (i < NN) g_deg[i] = 0u;
    }
}

// ============================================================================
// pack: fp16 packed B from W1 (k<256) and g_B2 (k>=256). 20 blocks x 256.
// ============================================================================
__global__ void pack_kernel(const float* __restrict__ W1) {
    const int kt = blockIdx.x;
    const int n  = threadIdx.x;
#pragma unroll
    for (int j = 0; j < 8; j++) {
        const int tg = j >> 1;
        const int kk = (j & 1) ? (2 * tg + 8) : (2 * tg);
        const int k0 = kt * 16 + kk;
        float f0, f1;
        if (k0 < H_DIM) {
            f0 = W1[(long long)k0 * OUT_DIM + n];
            f1 = W1[(long long)(k0 + 1) * OUT_DIM + n];
        } else {
            f0 = g_B2[(k0 - H_DIM) * 256 + n];
            f1 = g_B2[(k0 + 1 - H_DIM) * 256 + n];
        }
        g_Bpack[(kt * 256 + n) * 8 + j] = f16x2_pack(f0, f1);
    }
}

// ============================================================================
// CSR build
// ============================================================================
__global__ void hist_kernel(const int* __restrict__ dst_idx) {
    int e = blockIdx.x * blockDim.x + threadIdx.x;
    if (e < E_TOTAL) atomicAdd(&g_deg[dst_idx[e]], 1u);
}

__global__ void scan1_kernel() {
    __shared__ unsigned s[256];
    const int t = threadIdx.x;
    const int n = blockIdx.x * 256 + t;
    s[t] = (n < NN) ? g_deg[n] : 0u;
    __syncthreads();
#pragma unroll
    for (int d = 128; d > 0; d >>= 1) {
        if (t < d) s[t] += s[t + d];
        __syncthreads();
    }
    if (t == 0) g_bsum[blockIdx.x] = s[0];
}

__global__ void scan2_kernel() {
    __shared__ unsigned s[512];
    const int t = threadIdx.x;
    s[t] = (t < NBLK) ? g_bsum[t] : 0u;
    __syncthreads();
#pragma unroll
    for (int d = 1; d < 512; d <<= 1) {
        unsigned v = (t >= d) ? s[t - d] : 0u;
        __syncthreads();
        s[t] += v;
        __syncthreads();
    }
    if (t < NBLK) g_bsum[t] = (t == 0) ? 0u : s[t - 1];
}

__global__ void scan3_kernel() {
    __shared__ unsigned s[256];
    const int t = threadIdx.x;
    const int n = blockIdx.x * 256 + t;
    const unsigned d = (n < NN) ? g_deg[n] : 0u;
    s[t] = d;
    __syncthreads();
#pragma unroll
    for (int dd = 1; dd < 256; dd <<= 1) {
        unsigned v = (t >= dd) ? s[t - dd] : 0u;
        __syncthreads();
        s[t] += v;
        __syncthreads();
    }
    if (n < NN) {
        const unsigned off = g_bsum[blockIdx.x] + s[t] - d;
        g_off[n] = off;
        g_cursor[n] = off;
    }
}

__global__ void fill_kernel(const int* __restrict__ dst_idx) {
    int e = blockIdx.x * blockDim.x + threadIdx.x;
    if (e < E_TOTAL) {
        const unsigned pos = atomicAdd(&g_cursor[dst_idx[e]], 1u);
        g_eid[pos] = e;
    }
}

// ============================================================================
// Gather: g_Ah[n][256:320] = fp16(norm[n] * sum of edge_feat rows), no atomics.
// One warp per node; two half-warps, 8 edges in flight each.
// ============================================================================
__global__ __launch_bounds__(256) void gather_kernel(
    const float* __restrict__ edge_feat,   // [E, 64]
    const float* __restrict__ norm)        // [NN, 1]
{
    const int tid = threadIdx.x;
    const int warp = tid >> 5;
    const int lane = tid & 31;
    const int hw  = lane >> 4;
    const int l16 = lane & 15;

    const int n = blockIdx.x * 8 + warp;
    if (n >= NN) return;

    const unsigned off = g_off[n];
    const unsigned deg = g_deg[n];

    float4 acc = make_float4(0.f, 0.f, 0.f, 0.f);
    unsigned i = hw;
    for (; i + 14 < deg; i += 16) {
        float4 v[8];
#pragma unroll
        for (int u = 0; u < 8; u++) {
            const int e = g_eid[off + i + 2 * u];
            v[u] = *reinterpret_cast<const float4*>(
                edge_feat + (long long)e * EDGE_DIM + 4 * l16);
        }
#pragma unroll
        for (int u = 0; u < 8; u++) {
            acc.x += v[u].x; acc.y += v[u].y; acc.z += v[u].z; acc.w += v[u].w;
        }
    }
    for (; i < deg; i += 2) {
        const int e = g_eid[off + i];
        const float4 v = *reinterpret_cast<const float4*>(
            edge_feat + (long long)e * EDGE_DIM + 4 * l16);
        acc.x += v.x; acc.y += v.y; acc.z += v.z; acc.w += v.w;
    }
    acc.x += __shfl_xor_sync(0xffffffffu, acc.x, 16);
    acc.y += __shfl_xor_sync(0xffffffffu, acc.y, 16);
    acc.z += __shfl_xor_sync(0xffffffffu, acc.z, 16);
    acc.w += __shfl_xor_sync(0xffffffffu, acc.w, 16);
    if (hw == 0) {
        const float nr = norm[n];
        uint2 o;
        o.x = f16x2_pack(nr * acc.x, nr * acc.y);
        o.y = f16x2_pack(nr * acc.z, nr * acc.w);
        *reinterpret_cast<uint2*>(g_Ah + (long long)n * 320 + 256 + 4 * l16) = o;
    }
}

// ============================================================================
// Node GEMM: out = relu(g_Ah @ Bpack + norm*deg*v + b1)
// Pure fp16 GEMM with 4-stage cp.async pipeline. 128x128 tile, 256 threads.
// ============================================================================
#define ROW_TILES 782     // 782*128 = 100096 >= NN

__global__ __launch_bounds__(256, 2) void node_kernel(
    const float* __restrict__ norm,   // [NN, 1]
    const float* __restrict__ b1,     // [256]
    float* __restrict__ out)          // [NN, 256]
{
    __shared__ __align__(16) __half  As[NSTG][128][24];   // 24 KB (48B rows)
    __shared__ __align__(16) unsigned Bs[NSTG][128][8];   // 16 KB

    const int tid = threadIdx.x;
    const int wid = tid >> 5;
    const int lane = tid & 31;
    const int g  = lane >> 2;
    const int tg = lane & 3;
    const int wm = wid & 3;
    const int wn = wid >> 2;
    const int rt = blockIdx.x >> 1;
    const int cb = blockIdx.x & 1;
    const int row0 = rt * 128;
    const int col0 = cb * 128;

    // cp.async loader roles
    const int arow = tid >> 1;       // A row 0..127
    const int ap   = tid & 1;        // A 16B chunk 0/1
    const int bn   = tid >> 1;       // B n 0..127
    const int bp   = tid & 1;        // B 16B chunk 0/1

    const __half* asrc = g_Ah + (long long)(row0 + arow) * 320 + ap * 8;
    const unsigned* bsrc = g_Bpack + (long long)(col0 + bn) * 8 + bp * 4;

    unsigned a_dst[NSTG], b_dst[NSTG];
#pragma unroll
    for (int s = 0; s < NSTG; s++) {
        a_dst[s] = (unsigned)__cvta_generic_to_shared(&As[s][arow][ap * 8]);
        b_dst[s] = (unsigned)__cvta_generic_to_shared(&Bs[s][bn][bp * 4]);
    }

    // ldmatrix addresses per stage / m-tile
    unsigned lm_addr[NSTG][2];
#pragma unroll
    for (int s = 0; s < NSTG; s++)
#pragma unroll
        for (int mt = 0; mt < 2; mt++) {
            const int r = wm * 32 + mt * 16 + (lane & 15);
            lm_addr[s][mt] = (unsigned)__cvta_generic_to_shared(
                &As[s][r][(lane >> 4) * 8]);
        }

    float acc[2][8][4];
#pragma unroll
    for (int mt = 0; mt < 2; mt++)
#pragma unroll
        for (int nf = 0; nf < 8; nf++)
#pragma unroll
            for (int i = 0; i < 4; i++) acc[mt][nf][i] = 0.f;

    auto issue = [&](int kt) {
        if (kt < NKT) {
            const int s = kt & (NSTG - 1);
            cp_async16(a_dst[s], asrc + kt * 16);
            cp_async16(b_dst[s], bsrc + kt * 256 * 8);
        }
        asm volatile("cp.async.commit_group;");
    };

    issue(0); issue(1); issue(2);

    for (int kt = 0; kt < NKT; kt++) {
        const int s = kt & (NSTG - 1);
        asm volatile("cp.async.wait_group 2;");
        __syncthreads();
        issue(kt + 3);

        // B fragments: 8 conflict-free LDS.64, reused across both m-tiles
        unsigned bfr0[8], bfr1[8];
#pragma unroll
        for (int nf = 0; nf < 8; nf++) {
            const int cc = wn * 64 + nf * 8;
            const unsigned long long bb =
                *reinterpret_cast<const unsigned long long*>(&Bs[s][cc + g][2 * tg]);
            bfr0[nf] = (unsigned)bb;
            bfr1[nf] = (unsigned)(bb >> 32);
        }
#pragma unroll
        for (int mt = 0; mt < 2; mt++) {
            unsigned a0, a1, a2, a3;
            ldsm_x4(a0, a1, a2, a3, lm_addr[s][mt]);
#pragma unroll
            for (int nf = 0; nf < 8; nf++) {
                mma_f16(acc[mt][nf][0], acc[mt][nf][1],
                        acc[mt][nf][2], acc[mt][nf][3],
                        a0, a1, a2, a3, bfr0[nf], bfr1[nf]);
            }
        }
    }

    // epilogue: + norm*deg*v + bias, relu, store
    const int rbase = row0 + wm * 32 + g;
    float nd[4];
#pragma unroll
    for (int q = 0; q < 4; q++) {
        const int r = rbase + 8 * q;
        nd[q] = (r < NN) ? norm[r] * (float)g_deg[r] : 0.f;
    }

#pragma unroll
    for (int nf = 0; nf < 8; nf++) {
        const int col = col0 + wn * 64 + nf * 8 + 2 * tg;
        const float2 bb = *reinterpret_cast<const float2*>(b1 + col);
        const float2 vv = *reinterpret_cast<const float2*>(g_B2 + 64 * 256 + col);
#pragma unroll
        for (int mt = 0; mt < 2; mt++) {
            const int r = rbase + mt * 16;
            const float ndr = nd[mt * 2];
            if (r < NN) {
                float2 o;
                o.x = fmaxf(acc[mt][nf][0] + bb.x + ndr * vv.x, 0.f);
                o.y = fmaxf(acc[mt][nf][1] + bb.y + ndr * vv.y, 0.f);
                *reinterpret_cast<float2*>(out + (long long)r * OUT_DIM + col) = o;
            }
            const int r2 = r + 8;
            const float ndr2 = nd[mt * 2 + 1];
            if (r2 < NN) {
                float2 o;
                o.x = fmaxf(acc[mt][nf][2] + bb.x + ndr2 * vv.x, 0.f);
                o.y = fmaxf(acc[mt][nf][3] + bb.y + ndr2 * vv.y, 0.f);
                *reinterpret_cast<float2*>(out + (long long)r2 * OUT_DIM + col) = o;
            }
        }
    }
}

// ---------------- launch ----------------
extern "C" void kernel_launch(void* const* d_in, const int* in_sizes, int n_in,
                              void* d_out, int out_size) {
    const float* h         = (const float*)d_in[0];
    const float* edge_feat = (const float*)d_in[1];
    const float* norm      = (const float*)d_in[2];
    const float* W_msg     = (const float*)d_in[3];
    const float* b_msg     = (const float*)d_in[4];
    const float* W1        = (const float*)d_in[5];
    const float* b1        = (const float*)d_in[6];
    const int*   dst_idx   = (const int*)d_in[7];
    float* out = (float*)d_out;

    // independent precomputes
    conv_kernel<<<12500, 256>>>(h);                         // h -> fp16 A
    init_kernel<<<65 + NBLK, 256>>>(W_msg, b_msg, W1);      // W2/v + zero deg
    pack_kernel<<<NKT, 256>>>(W1);                          // fp16 packed B

    // CSR build
    hist_kernel<<<(E_TOTAL + 255) / 256, 256>>>(dst_idx);
    scan1_kernel<<<NBLK, 256>>>();
    scan2_kernel<<<1, 512>>>();
    scan3_kernel<<<NBLK, 256>>>();
    fill_kernel<<<(E_TOTAL + 255) / 256, 256>>>(dst_idx);

    // gather-sum raw edge features -> fp16 norm-scaled A tail
    gather_kernel<<<(NN + 7) / 8, 256>>>(edge_feat, norm);

    // pure fp16 GEMM node kernel + rank-1 deg term + bias + ReLU
    node_kernel<<<ROW_TILES * 2, 256>>>(norm, b1, out);
}

// round 12
// speedup vs baseline: 1.3060x; 1.0421x over previous
#include <cuda_runtime.h>
#include <cuda_fp16.h>

// Problem constants (fixed shapes per reference)
#define E_TOTAL   3200000
#define NN        100000
#define EDGE_DIM  64
#define ADDED     24
#define H_DIM     256
#define KDIM      280
#define OUT_DIM   256

#define SBLK      196      // scan blocks (512 nodes each; 196*512 >= NN)
#define NKT       20       // node k-tiles of 16 over K=320
#define NSTG      4        // cp.async pipeline stages

// ---- scratch (device globals; no runtime allocation) ----
// g_deg invariant: zero at entry of every kernel_launch call. Zero-initialized
// at load; node_kernel re-zeroes it at the end of every call.
__device__ unsigned g_deg[NN];
__device__ unsigned g_bsum[256];        // >= SBLK
__device__ unsigned g_off[NN];
__device__ unsigned g_cursor[NN];
__device__ int      g_eid[E_TOTAL];
__device__ float    g_nd[NN];           // norm[n] * deg[n] (written by gather)
__device__ float    g_B2[65 * 256];     // rows 0..63: W_msg@W1b ; row 64: b_msg@W1b
// fp16 A matrix [h | norm*S], row stride 320 halves. Rows >= NN stay zero.
__device__ __align__(16) __half g_Ah[100096 * 320];
// fp16 packed B: [kt][n][8 u32]
__device__ __align__(16) unsigned g_Bpack[NKT * 256 * 8];

// ---------------- helpers ----------------
__device__ __forceinline__ unsigned f16x2_pack(float lo, float hi) {
    unsigned u;
    asm("cvt.rn.f16x2.f32 %0, %1, %2;" : "=r"(u) : "f"(hi), "f"(lo));
    return u;
}
__device__ __forceinline__ void mma_f16(float& d0, float& d1, float& d2, float& d3,
                                        unsigned a0, unsigned a1, unsigned a2, unsigned a3,
                                        unsigned b0, unsigned b1) {
    asm volatile(
        "mma.sync.aligned.m16n8k16.row.col.f32.f16.f16.f32 "
        "{%0,%1,%2,%3}, {%4,%5,%6,%7}, {%8,%9}, {%0,%1,%2,%3};"
        : "+f"(d0), "+f"(d1), "+f"(d2), "+f"(d3)
        : "r"(a0), "r"(a1), "r"(a2), "r"(a3), "r"(b0), "r"(b1));
}
__device__ __forceinline__ void ldsm_x4(unsigned& r0, unsigned& r1, unsigned& r2, unsigned& r3,
                                        unsigned saddr) {
    asm volatile("ldmatrix.sync.aligned.m8n8.x4.shared.b16 {%0,%1,%2,%3}, [%4];"
                 : "=r"(r0), "=r"(r1), "=r"(r2), "=r"(r3) : "r"(saddr));
}
__device__ __forceinline__ void cp_async16(unsigned saddr, const void* gptr) {
    asm volatile("cp.async.cg.shared.global [%0], [%1], 16;"
                 :: "r"(saddr), "l"(gptr));
}

// ============================================================================
// K1: hist (blocks 0..12499) || conv h->fp16 (12500..24999) || B2 (25000..25064)
// All three roles are independent; hist's atomics require g_deg == 0 at entry
// (invariant maintained by node_kernel's tail).
// ============================================================================
__global__ void k1_kernel(const int* __restrict__ dst_idx,
                          const float* __restrict__ h,
                          const float* __restrict__ W_msg,
                          const float* __restrict__ b_msg,
                          const float* __restrict__ W1) {
    const int b = blockIdx.x;
    if (b < 12500) {
        // hist: 12500*256 == E_TOTAL exactly
        const int e = b * 256 + threadIdx.x;
        atomicAdd(&g_deg[dst_idx[e]], 1u);
    } else if (b < 25000) {
        // conv: 12500*256 == NN*32 exactly
        const long long t = (long long)(b - 12500) * 256 + threadIdx.x;
        const int row = (int)(t >> 5);
        const int kc  = (int)(t & 31) * 8;
        const float4 v0 = *reinterpret_cast<const float4*>(h + (long long)row * 256 + kc);
        const float4 v1 = *reinterpret_cast<const float4*>(h + (long long)row * 256 + kc + 4);
        uint4 o;
        o.x = f16x2_pack(v0.x, v0.y); o.y = f16x2_pack(v0.z, v0.w);
        o.z = f16x2_pack(v1.x, v1.y); o.w = f16x2_pack(v1.z, v1.w);
        *reinterpret_cast<uint4*>(g_Ah + (long long)row * 320 + kc) = o;
    } else {
        // B2 precompute: rows 0..64
        const int r = b - 25000;
        const int c = threadIdx.x;
        float acc = 0.f;
#pragma unroll
        for (int j = 0; j < ADDED; j++) {
            const float a = (r < EDGE_DIM) ? W_msg[r * ADDED + j] : b_msg[j];
            acc += a * W1[(long long)(H_DIM + j) * OUT_DIM + c];
        }
        g_B2[r * 256 + c] = acc;
    }
}

// ============================================================================
// K2: scan1 (blocks 0..195, 512 nodes each) || Bpack (blocks 196..215)
// ============================================================================
__global__ void k2_kernel(const float* __restrict__ W1) {
    if (blockIdx.x < SBLK) {
        __shared__ unsigned s[512];
        const int t = threadIdx.x;
        const int n = blockIdx.x * 512 + t;
        s[t] = (n < NN) ? g_deg[n] : 0u;
        __syncthreads();
#pragma unroll
        for (int d = 256; d > 0; d >>= 1) {
            if (t < d) s[t] += s[t + d];
            __syncthreads();
        }
        if (t == 0) g_bsum[blockIdx.x] = s[0];
    } else {
        // pack fp16 B: kt = blockIdx.x - SBLK; 512 threads cover (256 n) x (8 j)
        const int kt = blockIdx.x - SBLK;
        const int n  = threadIdx.x & 255;
        const int jb = (threadIdx.x >> 8) * 4;
#pragma unroll
        for (int jj = 0; jj < 4; jj++) {
            const int j = jb + jj;
            const int tg = j >> 1;
            const int kk = (j & 1) ? (2 * tg + 8) : (2 * tg);
            const int k0 = kt * 16 + kk;
            float f0, f1;
            if (k0 < H_DIM) {
                f0 = W1[(long long)k0 * OUT_DIM + n];
                f1 = W1[(long long)(k0 + 1) * OUT_DIM + n];
            } else {
                f0 = g_B2[(k0 - H_DIM) * 256 + n];
                f1 = g_B2[(k0 + 1 - H_DIM) * 256 + n];
            }
            g_Bpack[(kt * 256 + n) * 8 + j] = f16x2_pack(f0, f1);
        }
    }
}

// ============================================================================
// K3: fused scan2+scan3. Every block re-scans the 196 block sums in smem
// (cheaper than a separate launch), then does its local 512-wide scan.
// ============================================================================
__global__ void k3_kernel() {
    __shared__ unsigned bs[256];
    __shared__ unsigned s[512];
    const int t = threadIdx.x;

    if (t < 256) bs[t] = (t < SBLK) ? g_bsum[t] : 0u;
    __syncthreads();
#pragma unroll
    for (int d = 1; d < 256; d <<= 1) {
        unsigned v = 0u;
        if (t < 256 && t >= d) v = bs[t - d];
        __syncthreads();
        if (t < 256) bs[t] += v;
        __syncthreads();
    }
    const unsigned base = (blockIdx.x == 0) ? 0u : bs[blockIdx.x - 1];

    const int n = blockIdx.x * 512 + t;
    const unsigned dg = (n < NN) ? g_deg[n] : 0u;
    s[t] = dg;
    __syncthreads();
#pragma unroll
    for (int d = 1; d < 512; d <<= 1) {
        unsigned v = (t >= d) ? s[t - d] : 0u;
        __syncthreads();
        s[t] += v;
        __syncthreads();
    }
    if (n < NN) {
        const unsigned off = base + s[t] - dg;   // exclusive
        g_off[n] = off;
        g_cursor[n] = off;
    }
}

// ============================================================================
// K4: fill CSR edge ids
// ============================================================================
__global__ void fill_kernel(const int* __restrict__ dst_idx) {
    int e = blockIdx.x * blockDim.x + threadIdx.x;
    if (e < E_TOTAL) {
        const unsigned pos = atomicAdd(&g_cursor[dst_idx[e]], 1u);
        g_eid[pos] = e;
    }
}

// ============================================================================
// K5: gather. g_Ah[n][256:320] = fp16(norm*sum rows); g_nd[n] = norm*deg.
// One warp per node; two half-warps, 8 edges in flight each.
// ============================================================================
__global__ __launch_bounds__(256) void gather_kernel(
    const float* __restrict__ edge_feat,   // [E, 64]
    const float* __restrict__ norm)        // [NN, 1]
{
    const int tid = threadIdx.x;
    const int warp = tid >> 5;
    const int lane = tid & 31;
    const int hw  = lane >> 4;
    const int l16 = lane & 15;

    const int n = blockIdx.x * 8 + warp;
    if (n >= NN) return;

    const unsigned off = g_off[n];
    const unsigned deg = g_deg[n];

    float4 acc = make_float4(0.f, 0.f, 0.f, 0.f);
    unsigned i = hw;
    for (; i + 14 < deg; i += 16) {
        float4 v[8];
#pragma unroll
        for (int u = 0; u < 8; u++) {
            const int e = g_eid[off + i + 2 * u];
            v[u] = *reinterpret_cast<const float4*>(
                edge_feat + (long long)e * EDGE_DIM + 4 * l16);
        }
#pragma unroll
        for (int u = 0; u < 8; u++) {
            acc.x += v[u].x; acc.y += v[u].y; acc.z += v[u].z; acc.w += v[u].w;
        }
    }
    for (; i < deg; i += 2) {
        const int e = g_eid[off + i];
        const float4 v = *reinterpret_cast<const float4*>(
            edge_feat + (long long)e * EDGE_DIM + 4 * l16);
        acc.x += v.x; acc.y += v.y; acc.z += v.z; acc.w += v.w;
    }
    acc.x += __shfl_xor_sync(0xffffffffu, acc.x, 16);
    acc.y += __shfl_xor_sync(0xffffffffu, acc.y, 16);
    acc.z += __shfl_xor_sync(0xffffffffu, acc.z, 16);
    acc.w += __shfl_xor_sync(0xffffffffu, acc.w, 16);
    if (hw == 0) {
        const float nr = norm[n];
        uint2 o;
        o.x = f16x2_pack(nr * acc.x, nr * acc.y);
        o.y = f16x2_pack(nr * acc.z, nr * acc.w);
        *reinterpret_cast<uint2*>(g_Ah + (long long)n * 320 + 256 + 4 * l16) = o;
        if (l16 == 0) g_nd[n] = nr * (float)deg;
    }
}

// ============================================================================
// K6: node GEMM: out = relu(g_Ah @ Bpack + g_nd*v + b1)
// Pure fp16 GEMM, 4-stage cp.async pipeline. 128x128, 256 thr, 2 CTA/SM.
// Tail: cb==0 blocks re-zero g_deg rows (nothing reads g_deg after gather).
// ============================================================================
#define ROW_TILES 782     // 782*128 = 100096 >= NN

__global__ __launch_bounds__(256, 2) void node_kernel(
    const float* __restrict__ b1,     // [256]
    float* __restrict__ out)          // [NN, 256]
{
    __shared__ __align__(16) __half  As[NSTG][128][24];
    __shared__ __align__(16) unsigned Bs[NSTG][128][8];

    const int tid = threadIdx.x;
    const int wid = tid >> 5;
    const int lane = tid & 31;
    const int g  = lane >> 2;
    const int tg = lane & 3;
    const int wm = wid & 3;
    const int wn = wid >> 2;
    const int rt = blockIdx.x >> 1;
    const int cb = blockIdx.x & 1;
    const int row0 = rt * 128;
    const int col0 = cb * 128;

    const int arow = tid >> 1;
    const int ap   = tid & 1;
    const int bn   = tid >> 1;
    const int bp   = tid & 1;

    const __half* asrc = g_Ah + (long long)(row0 + arow) * 320 + ap * 8;
    const unsigned* bsrc = g_Bpack + (long long)(col0 + bn) * 8 + bp * 4;

    unsigned a_dst[NSTG], b_dst[NSTG];
#pragma unroll
    for (int s = 0; s < NSTG; s++) {
        a_dst[s] = (unsigned)__cvta_generic_to_shared(&As[s][arow][ap * 8]);
        b_dst[s] = (unsigned)__cvta_generic_to_shared(&Bs[s][bn][bp * 4]);
    }

    unsigned lm_addr[NSTG][2];
#pragma unroll
    for (int s = 0; s < NSTG; s++)
#pragma unroll
        for (int mt = 0; mt < 2; mt++) {
            const int r = wm * 32 + mt * 16 + (lane & 15);
            lm_addr[s][mt] = (unsigned)__cvta_generic_to_shared(
                &As[s][r][(lane >> 4) * 8]);
        }

    float acc[2][8][4];
#pragma unroll
    for (int mt = 0; mt < 2; mt++)
#pragma unroll
        for (int nf = 0; nf < 8; nf++)
#pragma unroll
            for (int i = 0; i < 4; i++) acc[mt][nf][i] = 0.f;

    auto issue = [&](int kt) {
        if (kt < NKT) {
            const int s = kt & (NSTG - 1);
            cp_async16(a_dst[s], asrc + kt * 16);
            cp_async16(b_dst[s], bsrc + kt * 256 * 8);
        }
        asm volatile("cp.async.commit_group;");
    };

    issue(0); issue(1); issue(2);

    for (int kt = 0; kt < NKT; kt++) {
        const int s = kt & (NSTG - 1);
        asm volatile("cp.async.wait_group 2;");
        __syncthreads();
        issue(kt + 3);

        unsigned bfr0[8], bfr1[8];
#pragma unroll
        for (int nf = 0; nf < 8; nf++) {
            const int cc = wn * 64 + nf * 8;
            const unsigned long long bb =
                *reinterpret_cast<const unsigned long long*>(&Bs[s][cc + g][2 * tg]);
            bfr0[nf] = (unsigned)bb;
            bfr1[nf] = (unsigned)(bb >> 32);
        }
#pragma unroll
        for (int mt = 0; mt < 2; mt++) {
            unsigned a0, a1, a2, a3;
            ldsm_x4(a0, a1, a2, a3, lm_addr[s][mt]);
#pragma unroll
            for (int nf = 0; nf < 8; nf++) {
                mma_f16(acc[mt][nf][0], acc[mt][nf][1],
                        acc[mt][nf][2], acc[mt][nf][3],
                        a0, a1, a2, a3, bfr0[nf], bfr1[nf]);
            }
        }
    }

    // epilogue: + g_nd*v + bias, relu, store
    const int rbase = row0 + wm * 32 + g;
    float nd[4];
#pragma unroll
    for (int q = 0; q < 4; q++) {
        const int r = rbase + 8 * q;
        nd[q] = (r < NN) ? g_nd[r] : 0.f;
    }

#pragma unroll
    for (int nf = 0; nf < 8; nf++) {
        const int col = col0 + wn * 64 + nf * 8 + 2 * tg;
        const float2 bb = *reinterpret_cast<const float2*>(b1 + col);
        const float2 vv = *reinterpret_cast<const float2*>(g_B2 + 64 * 256 + col);
#pragma unroll
        for (int mt = 0; mt < 2; mt++) {
            const int r = rbase + mt * 16;
            const float ndr = nd[mt * 2];
            if (r < NN) {
                float2 o;
                o.x = fmaxf(acc[mt][nf][0] + bb.x + ndr * vv.x, 0.f);
                o.y = fmaxf(acc[mt][nf][1] + bb.y + ndr * vv.y, 0.f);
                *reinterpret_cast<float2*>(out + (long long)r * OUT_DIM + col) = o;
            }
            const int r2 = r + 8;
            const float ndr2 = nd[mt * 2 + 1];
            if (r2 < NN) {
                float2 o;
                o.x = fmaxf(acc[mt][nf][2] + bb.x + ndr2 * vv.x, 0.f);
                o.y = fmaxf(acc[mt][nf][3] + bb.y + ndr2 * vv.y, 0.f);
                *reinterpret_cast<float2*>(out + (long long)r2 * OUT_DIM + col) = o;
            }
        }
    }

    // re-zero g_deg for the next call (nothing reads g_deg after gather;
    // epilogue used g_nd). cb==0 blocks only; one row per thread (tid<128).
    if (cb == 0 && tid < 128) {
        const int r = row0 + tid;
        if (r < NN) g_deg[r] = 0u;
    }
}

// ---------------- launch ----------------
extern "C" void kernel_launch(void* const* d_in, const int* in_sizes, int n_in,
                              void* d_out, int out_size) {
    const float* h         = (const float*)d_in[0];
    const float* edge_feat = (const float*)d_in[1];
    const float* norm      = (const float*)d_in[2];
    const float* W_msg     = (const float*)d_in[3];
    const float* b_msg     = (const float*)d_in[4];
    const float* W1        = (const float*)d_in[5];
    const float* b1        = (const float*)d_in[6];
    const int*   dst_idx   = (const int*)d_in[7];
    float* out = (float*)d_out;

    // K1: hist || conv || B2
    k1_kernel<<<25065, 256>>>(dst_idx, h, W_msg, b_msg, W1);
    // K2: scan1 || Bpack
    k2_kernel<<<SBLK + NKT, 512>>>(W1);
    // K3: scan2+scan3 fused
    k3_kernel<<<SBLK, 512>>>();
    // K4: fill CSR
    fill_kernel<<<(E_TOTAL + 255) / 256, 256>>>(dst_idx);
    // K5: gather (+ g_nd)
    gather_kernel<<<(NN + 7) / 8, 256>>>(edge_feat, norm);
    // K6: node GEMM + epilogue (+ g_deg re-zero)
    node_kernel<<<ROW_TILES * 2, 256>>>(b1, out);
}